// round 16
// baseline (speedup 1.0000x reference)
#include <cuda_runtime.h>
#include <cuda_fp16.h>
#include <cuda_bf16.h>
#include <math.h>
#include <stdint.h>

#define N_NODES 100000
#define C_DIM   128
#define E_EDGES 1600000

#define CHUNK   256
#define NBLK    ((N_NODES + CHUNK - 1) / CHUNK)   // 391

// ---- scratch (static __device__, no allocation) ----
__device__ __nv_bfloat16 g_wt_hi[C_DIM * C_DIM];  // W^T [n][k], bf16 hi
__device__ __nv_bfloat16 g_wt_lo[C_DIM * C_DIM];  // W^T [n][k], bf16 lo
__device__ __half g_xs[(size_t)N_NODES * C_DIM];  // (x @ w_new) * dinv[row], fp16
__device__ int    g_cnt[N_NODES];
__device__ float  g_dinv[N_NODES];
__device__ int    g_rowptr[N_NODES];
__device__ int    g_cur[N_NODES];
__device__ int    g_esrc[E_EDGES];
__device__ int    g_part[512];

__device__ __forceinline__ void bsplit(float v, __nv_bfloat16& h, __nv_bfloat16& l) {
    h = __float2bfloat16(v);
    l = __float2bfloat16(v - __bfloat162float(h));
}

// mma.sync m16n8k16 bf16 -> fp32 accumulate
__device__ __forceinline__ void mma16816(float* d, const uint32_t* a,
                                         uint32_t b0, uint32_t b1) {
    asm volatile(
        "mma.sync.aligned.m16n8k16.row.col.f32.bf16.bf16.f32 "
        "{%0,%1,%2,%3}, {%4,%5,%6,%7}, {%8,%9}, {%0,%1,%2,%3};"
        : "+f"(d[0]), "+f"(d[1]), "+f"(d[2]), "+f"(d[3])
        : "r"(a[0]), "r"(a[1]), "r"(a[2]), "r"(a[3]), "r"(b0), "r"(b1));
}

__device__ __forceinline__ void ldm_x4(uint32_t* r, uint32_t saddr) {
    asm volatile("ldmatrix.sync.aligned.m8n8.x4.shared.b16 {%0,%1,%2,%3}, [%4];"
                 : "=r"(r[0]), "=r"(r[1]), "=r"(r[2]), "=r"(r[3]) : "r"(saddr));
}

__device__ __forceinline__ uint32_t smem_u32(const void* p) {
    uint32_t a;
    asm("{ .reg .u64 t; cvta.to.shared.u64 t, %1; cvt.u32.u64 %0, t; }"
        : "=r"(a) : "l"(p));
    return a;
}

// ---------------------------------------------------------------------------
// Launch 1: LSTM single step -> W^T bf16 hi/lo; also zero g_cnt (fused init).
// ---------------------------------------------------------------------------
__global__ void k_wnew(const float* __restrict__ weight,
                       const float* __restrict__ w_ih,
                       const float* __restrict__ b_ih,
                       const float* __restrict__ b_hh) {
    for (int i = blockIdx.x * C_DIM + threadIdx.x; i < N_NODES; i += C_DIM * C_DIM)
        g_cnt[i] = 0;

    __shared__ __align__(16) float wrow[C_DIM];
    const int r = blockIdx.x;          // k index (row of W)
    const int c = threadIdx.x;         // n index (col of W)
    wrow[c] = weight[r * C_DIM + c];
    __syncthreads();

    const float4* wr4 = (const float4*)wrow;
    const float4* wi  = (const float4*)(w_ih + (size_t)(c) * C_DIM);
    const float4* wg  = (const float4*)(w_ih + (size_t)(2 * C_DIM + c) * C_DIM);
    const float4* wo  = (const float4*)(w_ih + (size_t)(3 * C_DIM + c) * C_DIM);

    float di = 0.f, dg = 0.f, dob = 0.f;
#pragma unroll
    for (int q = 0; q < C_DIM / 4; q++) {
        const float4 w4 = wr4[q];
        const float4 a = wi[q];
        const float4 b = wg[q];
        const float4 d = wo[q];
        di  = fmaf(w4.x, a.x, fmaf(w4.y, a.y, fmaf(w4.z, a.z, fmaf(w4.w, a.w, di))));
        dg  = fmaf(w4.x, b.x, fmaf(w4.y, b.y, fmaf(w4.z, b.z, fmaf(w4.w, b.w, dg))));
        dob = fmaf(w4.x, d.x, fmaf(w4.y, d.y, fmaf(w4.z, d.z, fmaf(w4.w, d.w, dob))));
    }
    const float iv = di  + b_ih[c]             + b_hh[c];
    const float gv = dg  + b_ih[2 * C_DIM + c] + b_hh[2 * C_DIM + c];
    const float ov = dob + b_ih[3 * C_DIM + c] + b_hh[3 * C_DIM + c];

    const float sig_i = 1.f / (1.f + __expf(-iv));
    const float sig_o = 1.f / (1.f + __expf(-ov));
    const float cst   = sig_i * tanhf(gv);
    const float wv    = sig_o * tanhf(cst);

    __nv_bfloat16 h, l;
    bsplit(wv, h, l);
    g_wt_hi[c * C_DIM + r] = h;     // transposed: [n][k]
    g_wt_lo[c * C_DIM + r] = l;
}

// Launch 2: degree histogram
__global__ void k_cnt(const int* __restrict__ dst) {
    const int e = blockIdx.x * blockDim.x + threadIdx.x;
    if (e < E_EDGES) atomicAdd(&g_cnt[dst[e]], 1);
}

// Launch 3: dinv = rsqrt(deg+1)
__global__ void k_dinv() {
    const int i = blockIdx.x * blockDim.x + threadIdx.x;
    if (i < N_NODES) g_dinv[i] = rsqrtf((float)(g_cnt[i] + 1));
}

// ---------------------------------------------------------------------------
// Launch 4 (profiled): tensor-core GEMM, ldmatrix loads, RAW-spread MMA order.
//   xs = (x @ w_new) * dinv[row] -> fp16 scratch.
// Block tile 256 rows x 128 cols, 512 threads (16 warps = 8m x 2n),
// warp tile 32x64. MMAs issued accumulator-rotating (reuse distance 4)
// so no back-to-back RAW on the same D fragment.
// ---------------------------------------------------------------------------
#define PITCH    136
#define ROWS_BLK 256
#define XHI_OFF  0
#define XLO_OFF  (ROWS_BLK * PITCH * 2)                 // 69632
#define WHI_OFF  (2 * ROWS_BLK * PITCH * 2)             // 139264
#define WLO_OFF  (WHI_OFF + C_DIM * PITCH * 2)          // 174080
#define SMEM_TOT (WLO_OFF + C_DIM * PITCH * 2)          // 208896

__global__ void __launch_bounds__(512, 1)
k_gemm(const float* __restrict__ x) {
    extern __shared__ __align__(16) char sm[];
    __nv_bfloat16* xhi = (__nv_bfloat16*)(sm + XHI_OFF);
    __nv_bfloat16* xlo = (__nv_bfloat16*)(sm + XLO_OFF);
    __nv_bfloat16* whi = (__nv_bfloat16*)(sm + WHI_OFF);
    __nv_bfloat16* wlo = (__nv_bfloat16*)(sm + WLO_OFF);

    const int tid = threadIdx.x;
    const int row0b = blockIdx.x * ROWS_BLK;

    // --- stage W^T hi/lo into padded smem (128 rows x 64 words) ---
#pragma unroll
    for (int it = 0; it < 16; it++) {
        const int i = tid + it * 512;           // 8192 words
        const int n = i >> 6, kw = i & 63;
        *(uint32_t*)(whi + n * PITCH + kw * 2) = ((const uint32_t*)g_wt_hi)[i];
        *(uint32_t*)(wlo + n * PITCH + kw * 2) = ((const uint32_t*)g_wt_lo)[i];
    }

    // --- load + split-convert x tile (2 threads per row) ---
    {
        const int xr = tid >> 1;                // 0..255
        const int xc = (tid & 1) * 64;          // col half
        int gr = row0b + xr;
        if (gr >= N_NODES) gr = 0;              // dummy row; stores guarded later
        const float4* src = (const float4*)(x + (size_t)gr * C_DIM + xc);
        __nv_bfloat16* dh = xhi + xr * PITCH + xc;
        __nv_bfloat16* dl = xlo + xr * PITCH + xc;
#pragma unroll
        for (int q = 0; q < 16; q++) {
            const float4 v = src[q];
            __nv_bfloat16 h0, l0, h1, l1, h2, l2, h3, l3;
            bsplit(v.x, h0, l0); bsplit(v.y, h1, l1);
            bsplit(v.z, h2, l2); bsplit(v.w, h3, l3);
            __nv_bfloat162 hh0 = {h0, h1}, hh1 = {h2, h3};
            __nv_bfloat162 ll0 = {l0, l1}, ll1 = {l2, l3};
            *(__nv_bfloat162*)(dh + q * 4)     = hh0;
            *(__nv_bfloat162*)(dh + q * 4 + 2) = hh1;
            *(__nv_bfloat162*)(dl + q * 4)     = ll0;
            *(__nv_bfloat162*)(dl + q * 4 + 2) = ll1;
        }
    }
    __syncthreads();

    // --- warp MMA mainloop ---
    const int wid = tid >> 5, lane = tid & 31;
    const int wm = wid >> 1, wn = wid & 1;
    const int grp = lane >> 2, ctr = lane & 3;
    const int rw = wm * 32;                 // warp row0 in block
    const int cw = wn * 64;                 // warp col0

    // ldmatrix lane->row maps
    const int a_lane = (lane & 15) * PITCH + 8 * (lane >> 4);
    const int b_lane = (8 * (lane >> 4) + (lane & 7)) * PITCH + 8 * ((lane >> 3) & 1);

    const uint32_t xhi_b = smem_u32(xhi) + (uint32_t)((rw * PITCH + a_lane) * 2);
    const uint32_t xlo_b = smem_u32(xlo) + (uint32_t)((rw * PITCH + a_lane) * 2);
    const uint32_t whi_b = smem_u32(whi) + (uint32_t)((cw * PITCH + b_lane) * 2);
    const uint32_t wlo_b = smem_u32(wlo) + (uint32_t)((cw * PITCH + b_lane) * 2);

    float d[2][8][4];
#pragma unroll
    for (int m = 0; m < 2; m++)
#pragma unroll
        for (int n = 0; n < 8; n++)
#pragma unroll
            for (int q = 0; q < 4; q++) d[m][n][q] = 0.f;

#pragma unroll
    for (int k0 = 0; k0 < C_DIM; k0 += 16) {
        uint32_t ah[2][4], al[2][4];
#pragma unroll
        for (int m = 0; m < 2; m++) {
            ldm_x4(ah[m], xhi_b + (uint32_t)((m * 16 * PITCH + k0) * 2));
            ldm_x4(al[m], xlo_b + (uint32_t)((m * 16 * PITCH + k0) * 2));
        }
#pragma unroll
        for (int j = 0; j < 4; j++) {       // 4 pairs of n8-tiles
            uint32_t bh[4], bl[4];
            ldm_x4(bh, whi_b + (uint32_t)((j * 16 * PITCH + k0) * 2));
            ldm_x4(bl, wlo_b + (uint32_t)((j * 16 * PITCH + k0) * 2));
            // term-major, accumulator-rotating: reuse distance 4 (no
            // back-to-back RAW on the same accumulator fragment).
            mma16816(d[0][2 * j],     ah[0], bh[0], bh[1]);   // hi*hi
            mma16816(d[0][2 * j + 1], ah[0], bh[2], bh[3]);
            mma16816(d[1][2 * j],     ah[1], bh[0], bh[1]);
            mma16816(d[1][2 * j + 1], ah[1], bh[2], bh[3]);
            mma16816(d[0][2 * j],     al[0], bh[0], bh[1]);   // lo*hi
            mma16816(d[0][2 * j + 1], al[0], bh[2], bh[3]);
            mma16816(d[1][2 * j],     al[1], bh[0], bh[1]);
            mma16816(d[1][2 * j + 1], al[1], bh[2], bh[3]);
            mma16816(d[0][2 * j],     ah[0], bl[0], bl[1]);   // hi*lo
            mma16816(d[0][2 * j + 1], ah[0], bl[2], bl[3]);
            mma16816(d[1][2 * j],     ah[1], bl[0], bl[1]);
            mma16816(d[1][2 * j + 1], ah[1], bl[2], bl[3]);
        }
    }

    // --- epilogue: scale by dinv[row], convert fp16, store g_xs ---
#pragma unroll
    for (int m = 0; m < 2; m++) {
        const int r1 = row0b + rw + m * 16 + grp;
        const int r2 = r1 + 8;
        const float dv1 = (r1 < N_NODES) ? g_dinv[r1] : 0.f;
        const float dv2 = (r2 < N_NODES) ? g_dinv[r2] : 0.f;
#pragma unroll
        for (int n = 0; n < 8; n++) {
            const int col = cw + n * 8 + 2 * ctr;
            if (r1 < N_NODES) {
                const __half2 h = __floats2half2_rn(d[m][n][0] * dv1, d[m][n][1] * dv1);
                *(__half2*)((char*)g_xs + ((size_t)r1 * C_DIM + col) * 2) = h;
            }
            if (r2 < N_NODES) {
                const __half2 h = __floats2half2_rn(d[m][n][2] * dv2, d[m][n][3] * dv2);
                *(__half2*)((char*)g_xs + ((size_t)r2 * C_DIM + col) * 2) = h;
            }
        }
    }
}

// ---------------------------------------------------------------------------
// CSR build: per-chunk sums -> scan -> rowptr -> fill
// ---------------------------------------------------------------------------
__global__ void k_part() {
    __shared__ int sh[CHUNK];
    const int t = threadIdx.x;
    const int i = blockIdx.x * CHUNK + t;
    sh[t] = (i < N_NODES) ? g_cnt[i] : 0;
    __syncthreads();
    for (int off = CHUNK / 2; off > 0; off >>= 1) {
        if (t < off) sh[t] += sh[t + off];
        __syncthreads();
    }
    if (t == 0) g_part[blockIdx.x] = sh[0];
}

__global__ void k_scanpart() {
    __shared__ int sh[512];
    const int t = threadIdx.x;
    const int v = (t < NBLK) ? g_part[t] : 0;
    sh[t] = v;
    __syncthreads();
#pragma unroll
    for (int off = 1; off < 512; off <<= 1) {
        const int u = (t >= off) ? sh[t - off] : 0;
        __syncthreads();
        sh[t] += u;
        __syncthreads();
    }
    if (t < NBLK) g_part[t] = sh[t] - v;   // exclusive
}

__global__ void k_rowptr() {
    __shared__ int sh[CHUNK];
    const int t = threadIdx.x;
    const int i = blockIdx.x * CHUNK + t;
    const int v = (i < N_NODES) ? g_cnt[i] : 0;
    sh[t] = v;
    __syncthreads();
#pragma unroll
    for (int off = 1; off < CHUNK; off <<= 1) {
        const int u = (t >= off) ? sh[t - off] : 0;
        __syncthreads();
        sh[t] += u;
        __syncthreads();
    }
    if (i < N_NODES) {
        const int rp = g_part[blockIdx.x] + sh[t] - v;
        g_rowptr[i] = rp;
        g_cur[i]    = rp;
    }
}

__global__ void k_fill(const int* __restrict__ srcA, const int* __restrict__ dstA) {
    const int e = blockIdx.x * blockDim.x + threadIdx.x;
    if (e < E_EDGES) {
        const int pos = atomicAdd(&g_cur[dstA[e]], 1);
        g_esrc[pos] = srcA[e];
    }
}

// ---------------------------------------------------------------------------
// CSR accumulate: one warp per node, fp16 gather, fp32 accumulate.
// ---------------------------------------------------------------------------
__global__ void k_accum(float* __restrict__ out) {
    const int warp = (blockIdx.x * blockDim.x + threadIdx.x) >> 5;
    const int lane = threadIdx.x & 31;
    if (warp >= N_NODES) return;

    const int node  = warp;
    const int base  = g_rowptr[node];
    const int cnt   = g_cnt[node];
    const float dv  = g_dinv[node];

    float4 acc;
    {
        const __half2* p = (const __half2*)((const char*)g_xs + ((size_t)node * C_DIM + lane * 4) * 2);
        const float2 a = __half22float2(p[0]);
        const float2 b = __half22float2(p[1]);
        acc.x = a.x; acc.y = a.y; acc.z = b.x; acc.w = b.y;
    }

    for (int j0 = 0; j0 < cnt; j0 += 32) {
        const int j = j0 + lane;
        const int s = (j < cnt) ? g_esrc[base + j] : 0;
        const int m = min(32, cnt - j0);
#pragma unroll 4
        for (int i = 0; i < m; i++) {
            const int ss = __shfl_sync(0xffffffffu, s, i);
            const uint2 raw = *(const uint2*)((const char*)g_xs + ((size_t)ss * C_DIM + lane * 4) * 2);
            const float2 a = __half22float2(*(const __half2*)&raw.x);
            const float2 b = __half22float2(*(const __half2*)&raw.y);
            acc.x += a.x; acc.y += a.y; acc.z += b.x; acc.w += b.y;
        }
    }

    float4 o;
    o.x = acc.x * dv; o.y = acc.y * dv; o.z = acc.z * dv; o.w = acc.w * dv;
    *(float4*)(out + (size_t)node * C_DIM + lane * 4) = o;
}

// ---------------------------------------------------------------------------
// Launch
// inputs: 0:x[N,C] 1:edge_index[2,E] 2:weight[C,C] 3:w_ih[4C,C] 4:w_hh 5:b_ih 6:b_hh
// ---------------------------------------------------------------------------
extern "C" void kernel_launch(void* const* d_in, const int* in_sizes, int n_in,
                              void* d_out, int out_size) {
    const float* x      = (const float*)d_in[0];
    const int*   ei     = (const int*)  d_in[1];
    const float* weight = (const float*)d_in[2];
    const float* w_ih   = (const float*)d_in[3];
    const float* b_ih   = (const float*)d_in[5];
    const float* b_hh   = (const float*)d_in[6];
    float* out = (float*)d_out;

    const int* srcA = ei;
    const int* dstA = ei + E_EDGES;

    k_wnew<<<C_DIM, C_DIM>>>(weight, w_ih, b_ih, b_hh);            // 1
    k_cnt<<<(E_EDGES + 255) / 256, 256>>>(dstA);                   // 2
    k_dinv<<<(N_NODES + 255) / 256, 256>>>();                      // 3

    cudaFuncSetAttribute(k_gemm, cudaFuncAttributeMaxDynamicSharedMemorySize, SMEM_TOT);
    k_gemm<<<(N_NODES + ROWS_BLK - 1) / ROWS_BLK, 512, SMEM_TOT>>>(x);  // 4 <- profiled

    k_part<<<NBLK, CHUNK>>>();                                     // 5
    k_scanpart<<<1, 512>>>();                                      // 6
    k_rowptr<<<NBLK, CHUNK>>>();                                   // 7
    k_fill<<<(E_EDGES + 255) / 256, 256>>>(srcA, dstA);            // 8

    k_accum<<<(N_NODES * 32 + 255) / 256, 256>>>(out);             // 9
}

// round 17
// speedup vs baseline: 1.1073x; 1.1073x over previous
#include <cuda_runtime.h>
#include <cuda_fp16.h>
#include <cuda_bf16.h>
#include <math.h>
#include <stdint.h>

#define N_NODES 100000
#define C_DIM   128
#define E_EDGES 1600000

#define CHUNK   256
#define NBLK    ((N_NODES + CHUNK - 1) / CHUNK)   // 391

// ---- scratch (static __device__, no allocation) ----
__device__ __nv_bfloat16 g_wt_hi[C_DIM * C_DIM];  // W^T [n][k], bf16 hi
__device__ __nv_bfloat16 g_wt_lo[C_DIM * C_DIM];  // W^T [n][k], bf16 lo
__device__ __half g_xs[(size_t)N_NODES * C_DIM];  // (x @ w_new) * dinv[row], fp16
__device__ int    g_cnt[N_NODES];
__device__ float  g_dinv[N_NODES];
__device__ int    g_rowptr[N_NODES];
__device__ int    g_cur[N_NODES];
__device__ int    g_esrc[E_EDGES];
__device__ int    g_part[512];

__device__ __forceinline__ void bsplit(float v, __nv_bfloat16& h, __nv_bfloat16& l) {
    h = __float2bfloat16(v);
    l = __float2bfloat16(v - __bfloat162float(h));
}

// mma.sync m16n8k16 bf16 -> fp32 accumulate
__device__ __forceinline__ void mma16816(float* d, const uint32_t* a,
                                         uint32_t b0, uint32_t b1) {
    asm volatile(
        "mma.sync.aligned.m16n8k16.row.col.f32.bf16.bf16.f32 "
        "{%0,%1,%2,%3}, {%4,%5,%6,%7}, {%8,%9}, {%0,%1,%2,%3};"
        : "+f"(d[0]), "+f"(d[1]), "+f"(d[2]), "+f"(d[3])
        : "r"(a[0]), "r"(a[1]), "r"(a[2]), "r"(a[3]), "r"(b0), "r"(b1));
}

__device__ __forceinline__ void ldm_x4(uint32_t* r, uint32_t saddr) {
    asm volatile("ldmatrix.sync.aligned.m8n8.x4.shared.b16 {%0,%1,%2,%3}, [%4];"
                 : "=r"(r[0]), "=r"(r[1]), "=r"(r[2]), "=r"(r[3]) : "r"(saddr));
}

__device__ __forceinline__ uint32_t smem_u32(const void* p) {
    uint32_t a;
    asm("{ .reg .u64 t; cvta.to.shared.u64 t, %1; cvt.u32.u64 %0, t; }"
        : "=r"(a) : "l"(p));
    return a;
}

// ---------------------------------------------------------------------------
// Launch 1: LSTM single step -> W^T bf16 hi/lo; also zero g_cnt (fused init).
// ---------------------------------------------------------------------------
__global__ void k_wnew(const float* __restrict__ weight,
                       const float* __restrict__ w_ih,
                       const float* __restrict__ b_ih,
                       const float* __restrict__ b_hh) {
    for (int i = blockIdx.x * C_DIM + threadIdx.x; i < N_NODES; i += C_DIM * C_DIM)
        g_cnt[i] = 0;

    __shared__ __align__(16) float wrow[C_DIM];
    const int r = blockIdx.x;          // k index (row of W)
    const int c = threadIdx.x;         // n index (col of W)
    wrow[c] = weight[r * C_DIM + c];
    __syncthreads();

    const float4* wr4 = (const float4*)wrow;
    const float4* wi  = (const float4*)(w_ih + (size_t)(c) * C_DIM);
    const float4* wg  = (const float4*)(w_ih + (size_t)(2 * C_DIM + c) * C_DIM);
    const float4* wo  = (const float4*)(w_ih + (size_t)(3 * C_DIM + c) * C_DIM);

    float di = 0.f, dg = 0.f, dob = 0.f;
#pragma unroll
    for (int q = 0; q < C_DIM / 4; q++) {
        const float4 w4 = wr4[q];
        const float4 a = wi[q];
        const float4 b = wg[q];
        const float4 d = wo[q];
        di  = fmaf(w4.x, a.x, fmaf(w4.y, a.y, fmaf(w4.z, a.z, fmaf(w4.w, a.w, di))));
        dg  = fmaf(w4.x, b.x, fmaf(w4.y, b.y, fmaf(w4.z, b.z, fmaf(w4.w, b.w, dg))));
        dob = fmaf(w4.x, d.x, fmaf(w4.y, d.y, fmaf(w4.z, d.z, fmaf(w4.w, d.w, dob))));
    }
    const float iv = di  + b_ih[c]             + b_hh[c];
    const float gv = dg  + b_ih[2 * C_DIM + c] + b_hh[2 * C_DIM + c];
    const float ov = dob + b_ih[3 * C_DIM + c] + b_hh[3 * C_DIM + c];

    const float sig_i = 1.f / (1.f + __expf(-iv));
    const float sig_o = 1.f / (1.f + __expf(-ov));
    const float cst   = sig_i * tanhf(gv);
    const float wv    = sig_o * tanhf(cst);

    __nv_bfloat16 h, l;
    bsplit(wv, h, l);
    g_wt_hi[c * C_DIM + r] = h;     // transposed: [n][k]
    g_wt_lo[c * C_DIM + r] = l;
}

// Launch 2: degree histogram
__global__ void k_cnt(const int* __restrict__ dst) {
    const int e = blockIdx.x * blockDim.x + threadIdx.x;
    if (e < E_EDGES) atomicAdd(&g_cnt[dst[e]], 1);
}

// dinv = rsqrt(deg+1)
__global__ void k_dinv() {
    const int i = blockIdx.x * blockDim.x + threadIdx.x;
    if (i < N_NODES) g_dinv[i] = rsqrtf((float)(g_cnt[i] + 1));
}

// ---------------------------------------------------------------------------
// Tensor-core GEMM (best known config, R15):
//   xs = (x @ w_new) * dinv[row] -> fp16 scratch.
// Block tile 256x128, 512 threads, ldmatrix loads, RAW-spread MMA order.
// ---------------------------------------------------------------------------
#define PITCH    136
#define ROWS_BLK 256
#define XHI_OFF  0
#define XLO_OFF  (ROWS_BLK * PITCH * 2)                 // 69632
#define WHI_OFF  (2 * ROWS_BLK * PITCH * 2)             // 139264
#define WLO_OFF  (WHI_OFF + C_DIM * PITCH * 2)          // 174080
#define SMEM_TOT (WLO_OFF + C_DIM * PITCH * 2)          // 208896

__global__ void __launch_bounds__(512, 1)
k_gemm(const float* __restrict__ x) {
    extern __shared__ __align__(16) char sm[];
    __nv_bfloat16* xhi = (__nv_bfloat16*)(sm + XHI_OFF);
    __nv_bfloat16* xlo = (__nv_bfloat16*)(sm + XLO_OFF);
    __nv_bfloat16* whi = (__nv_bfloat16*)(sm + WHI_OFF);
    __nv_bfloat16* wlo = (__nv_bfloat16*)(sm + WLO_OFF);

    const int tid = threadIdx.x;
    const int row0b = blockIdx.x * ROWS_BLK;

    // --- stage W^T hi/lo into padded smem (128 rows x 64 words) ---
#pragma unroll
    for (int it = 0; it < 16; it++) {
        const int i = tid + it * 512;           // 8192 words
        const int n = i >> 6, kw = i & 63;
        *(uint32_t*)(whi + n * PITCH + kw * 2) = ((const uint32_t*)g_wt_hi)[i];
        *(uint32_t*)(wlo + n * PITCH + kw * 2) = ((const uint32_t*)g_wt_lo)[i];
    }

    // --- load + split-convert x tile (2 threads per row) ---
    {
        const int xr = tid >> 1;                // 0..255
        const int xc = (tid & 1) * 64;          // col half
        int gr = row0b + xr;
        if (gr >= N_NODES) gr = 0;              // dummy row; stores guarded later
        const float4* src = (const float4*)(x + (size_t)gr * C_DIM + xc);
        __nv_bfloat16* dh = xhi + xr * PITCH + xc;
        __nv_bfloat16* dl = xlo + xr * PITCH + xc;
#pragma unroll
        for (int q = 0; q < 16; q++) {
            const float4 v = src[q];
            __nv_bfloat16 h0, l0, h1, l1, h2, l2, h3, l3;
            bsplit(v.x, h0, l0); bsplit(v.y, h1, l1);
            bsplit(v.z, h2, l2); bsplit(v.w, h3, l3);
            __nv_bfloat162 hh0 = {h0, h1}, hh1 = {h2, h3};
            __nv_bfloat162 ll0 = {l0, l1}, ll1 = {l2, l3};
            *(__nv_bfloat162*)(dh + q * 4)     = hh0;
            *(__nv_bfloat162*)(dh + q * 4 + 2) = hh1;
            *(__nv_bfloat162*)(dl + q * 4)     = ll0;
            *(__nv_bfloat162*)(dl + q * 4 + 2) = ll1;
        }
    }
    __syncthreads();

    // --- warp MMA mainloop ---
    const int wid = tid >> 5, lane = tid & 31;
    const int wm = wid >> 1, wn = wid & 1;
    const int grp = lane >> 2, ctr = lane & 3;
    const int rw = wm * 32;                 // warp row0 in block
    const int cw = wn * 64;                 // warp col0

    const int a_lane = (lane & 15) * PITCH + 8 * (lane >> 4);
    const int b_lane = (8 * (lane >> 4) + (lane & 7)) * PITCH + 8 * ((lane >> 3) & 1);

    const uint32_t xhi_b = smem_u32(xhi) + (uint32_t)((rw * PITCH + a_lane) * 2);
    const uint32_t xlo_b = smem_u32(xlo) + (uint32_t)((rw * PITCH + a_lane) * 2);
    const uint32_t whi_b = smem_u32(whi) + (uint32_t)((cw * PITCH + b_lane) * 2);
    const uint32_t wlo_b = smem_u32(wlo) + (uint32_t)((cw * PITCH + b_lane) * 2);

    float d[2][8][4];
#pragma unroll
    for (int m = 0; m < 2; m++)
#pragma unroll
        for (int n = 0; n < 8; n++)
#pragma unroll
            for (int q = 0; q < 4; q++) d[m][n][q] = 0.f;

#pragma unroll
    for (int k0 = 0; k0 < C_DIM; k0 += 16) {
        uint32_t ah[2][4], al[2][4];
#pragma unroll
        for (int m = 0; m < 2; m++) {
            ldm_x4(ah[m], xhi_b + (uint32_t)((m * 16 * PITCH + k0) * 2));
            ldm_x4(al[m], xlo_b + (uint32_t)((m * 16 * PITCH + k0) * 2));
        }
#pragma unroll
        for (int j = 0; j < 4; j++) {       // 4 pairs of n8-tiles
            uint32_t bh[4], bl[4];
            ldm_x4(bh, whi_b + (uint32_t)((j * 16 * PITCH + k0) * 2));
            ldm_x4(bl, wlo_b + (uint32_t)((j * 16 * PITCH + k0) * 2));
            mma16816(d[0][2 * j],     ah[0], bh[0], bh[1]);   // hi*hi
            mma16816(d[0][2 * j + 1], ah[0], bh[2], bh[3]);
            mma16816(d[1][2 * j],     ah[1], bh[0], bh[1]);
            mma16816(d[1][2 * j + 1], ah[1], bh[2], bh[3]);
            mma16816(d[0][2 * j],     al[0], bh[0], bh[1]);   // lo*hi
            mma16816(d[0][2 * j + 1], al[0], bh[2], bh[3]);
            mma16816(d[1][2 * j],     al[1], bh[0], bh[1]);
            mma16816(d[1][2 * j + 1], al[1], bh[2], bh[3]);
            mma16816(d[0][2 * j],     ah[0], bl[0], bl[1]);   // hi*lo
            mma16816(d[0][2 * j + 1], ah[0], bl[2], bl[3]);
            mma16816(d[1][2 * j],     ah[1], bl[0], bl[1]);
            mma16816(d[1][2 * j + 1], ah[1], bl[2], bl[3]);
        }
    }

    // --- epilogue: scale by dinv[row], convert fp16, store g_xs ---
#pragma unroll
    for (int m = 0; m < 2; m++) {
        const int r1 = row0b + rw + m * 16 + grp;
        const int r2 = r1 + 8;
        const float dv1 = (r1 < N_NODES) ? g_dinv[r1] : 0.f;
        const float dv2 = (r2 < N_NODES) ? g_dinv[r2] : 0.f;
#pragma unroll
        for (int n = 0; n < 8; n++) {
            const int col = cw + n * 8 + 2 * ctr;
            if (r1 < N_NODES) {
                const __half2 h = __floats2half2_rn(d[m][n][0] * dv1, d[m][n][1] * dv1);
                *(__half2*)((char*)g_xs + ((size_t)r1 * C_DIM + col) * 2) = h;
            }
            if (r2 < N_NODES) {
                const __half2 h = __floats2half2_rn(d[m][n][2] * dv2, d[m][n][3] * dv2);
                *(__half2*)((char*)g_xs + ((size_t)r2 * C_DIM + col) * 2) = h;
            }
        }
    }
}

// ---------------------------------------------------------------------------
// CSR build: per-chunk sums -> scan -> rowptr -> fill
// ---------------------------------------------------------------------------
__global__ void k_part() {
    __shared__ int sh[CHUNK];
    const int t = threadIdx.x;
    const int i = blockIdx.x * CHUNK + t;
    sh[t] = (i < N_NODES) ? g_cnt[i] : 0;
    __syncthreads();
    for (int off = CHUNK / 2; off > 0; off >>= 1) {
        if (t < off) sh[t] += sh[t + off];
        __syncthreads();
    }
    if (t == 0) g_part[blockIdx.x] = sh[0];
}

__global__ void k_scanpart() {
    __shared__ int sh[512];
    const int t = threadIdx.x;
    const int v = (t < NBLK) ? g_part[t] : 0;
    sh[t] = v;
    __syncthreads();
#pragma unroll
    for (int off = 1; off < 512; off <<= 1) {
        const int u = (t >= off) ? sh[t - off] : 0;
        __syncthreads();
        sh[t] += u;
        __syncthreads();
    }
    if (t < NBLK) g_part[t] = sh[t] - v;   // exclusive
}

__global__ void k_rowptr() {
    __shared__ int sh[CHUNK];
    const int t = threadIdx.x;
    const int i = blockIdx.x * CHUNK + t;
    const int v = (i < N_NODES) ? g_cnt[i] : 0;
    sh[t] = v;
    __syncthreads();
#pragma unroll
    for (int off = 1; off < CHUNK; off <<= 1) {
        const int u = (t >= off) ? sh[t - off] : 0;
        __syncthreads();
        sh[t] += u;
        __syncthreads();
    }
    if (i < N_NODES) {
        const int rp = g_part[blockIdx.x] + sh[t] - v;
        g_rowptr[i] = rp;
        g_cur[i]    = rp;
    }
}

__global__ void k_fill(const int* __restrict__ srcA, const int* __restrict__ dstA) {
    const int e = blockIdx.x * blockDim.x + threadIdx.x;
    if (e < E_EDGES) {
        const int pos = atomicAdd(&g_cur[dstA[e]], 1);
        g_esrc[pos] = srcA[e];
    }
}

// ---------------------------------------------------------------------------
// CSR accumulate: one warp per node, fp16 gather, fp32 accumulate.
// ---------------------------------------------------------------------------
__global__ void k_accum(float* __restrict__ out) {
    const int warp = (blockIdx.x * blockDim.x + threadIdx.x) >> 5;
    const int lane = threadIdx.x & 31;
    if (warp >= N_NODES) return;

    const int node  = warp;
    const int base  = g_rowptr[node];
    const int cnt   = g_cnt[node];
    const float dv  = g_dinv[node];

    float4 acc;
    {
        const __half2* p = (const __half2*)((const char*)g_xs + ((size_t)node * C_DIM + lane * 4) * 2);
        const float2 a = __half22float2(p[0]);
        const float2 b = __half22float2(p[1]);
        acc.x = a.x; acc.y = a.y; acc.z = b.x; acc.w = b.y;
    }

    for (int j0 = 0; j0 < cnt; j0 += 32) {
        const int j = j0 + lane;
        const int s = (j < cnt) ? g_esrc[base + j] : 0;
        const int m = min(32, cnt - j0);
#pragma unroll 4
        for (int i = 0; i < m; i++) {
            const int ss = __shfl_sync(0xffffffffu, s, i);
            const uint2 raw = *(const uint2*)((const char*)g_xs + ((size_t)ss * C_DIM + lane * 4) * 2);
            const float2 a = __half22float2(*(const __half2*)&raw.x);
            const float2 b = __half22float2(*(const __half2*)&raw.y);
            acc.x += a.x; acc.y += a.y; acc.z += b.x; acc.w += b.y;
        }
    }

    float4 o;
    o.x = acc.x * dv; o.y = acc.y * dv; o.z = acc.z * dv; o.w = acc.w * dv;
    *(float4*)(out + (size_t)node * C_DIM + lane * 4) = o;
}

// ---------------------------------------------------------------------------
// Launch: fork/join graph.
//   main:  wnew -> cnt -> dinv -> gemm ----------------+-> accum
//   side:          \-> part -> scanpart -> rowptr -> fill/
// inputs: 0:x[N,C] 1:edge_index[2,E] 2:weight[C,C] 3:w_ih[4C,C] 4:w_hh 5:b_ih 6:b_hh
// ---------------------------------------------------------------------------
extern "C" void kernel_launch(void* const* d_in, const int* in_sizes, int n_in,
                              void* d_out, int out_size) {
    const float* x      = (const float*)d_in[0];
    const int*   ei     = (const int*)  d_in[1];
    const float* weight = (const float*)d_in[2];
    const float* w_ih   = (const float*)d_in[3];
    const float* b_ih   = (const float*)d_in[5];
    const float* b_hh   = (const float*)d_in[6];
    float* out = (float*)d_out;

    const int* srcA = ei;
    const int* dstA = ei + E_EDGES;

    // one-time host-side resources (no device memory involved)
    static cudaStream_t s2 = nullptr;
    static cudaEvent_t evFork = nullptr, evJoin = nullptr;
    if (s2 == nullptr) {
        cudaStreamCreateWithFlags(&s2, cudaStreamNonBlocking);
        cudaEventCreateWithFlags(&evFork, cudaEventDisableTiming);
        cudaEventCreateWithFlags(&evJoin, cudaEventDisableTiming);
        cudaFuncSetAttribute(k_gemm, cudaFuncAttributeMaxDynamicSharedMemorySize, SMEM_TOT);
    }

    // main chain
    k_wnew<<<C_DIM, C_DIM>>>(weight, w_ih, b_ih, b_hh);
    k_cnt<<<(E_EDGES + 255) / 256, 256>>>(dstA);

    // fork: CSR build on side stream (depends only on g_cnt)
    cudaEventRecord(evFork, 0);
    cudaStreamWaitEvent(s2, evFork, 0);
    k_part<<<NBLK, CHUNK, 0, s2>>>();
    k_scanpart<<<1, 512, 0, s2>>>();
    k_rowptr<<<NBLK, CHUNK, 0, s2>>>();
    k_fill<<<(E_EDGES + 255) / 256, 256, 0, s2>>>(srcA, dstA);
    cudaEventRecord(evJoin, s2);

    // main chain continues: dinv + GEMM (independent of CSR build)
    k_dinv<<<(N_NODES + 255) / 256, 256>>>();
    k_gemm<<<(N_NODES + ROWS_BLK - 1) / ROWS_BLK, 512, SMEM_TOT>>>(x);

    // join, then accumulate
    cudaStreamWaitEvent(0, evJoin, 0);
    k_accum<<<(N_NODES * 32 + 255) / 256, 256>>>(out);
}